// round 14
// baseline (speedup 1.0000x reference)
#include <cuda_runtime.h>

// Problem constants (fixed shapes from reference setup_inputs)
#define BB 16
#define SS 64
#define II 128
#define HH 512
#define TT 5
#define H4 (HH / 4)       // 128 float4 lanes across H
#define NPROD 148         // one producer CTA per SM (classic LUT bijection)
#define NCONS 32          // 8192 chains / 256 threads
#define NITEMS 512        // 4 k-chunks x 8 h-slices x 16 b

// Scratch: cur[b,s,h] = sum_i x[b,s,i,h] * enc[i,h]   (2 MB)
__device__ float g_cur[BB * SS * HH];
// Per-(k,b) completion counters: flag[k*16+b] counts finished h-slices (0..8)
__device__ int g_flags[64];

__global__ void init_flags_kernel() {
    g_flags[threadIdx.x] = 0;
}

// ---------------------------------------------------------------------------
// Fused kernel.
// Producers (bid < 148): persistent loop over 512 reduce tiles ordered
// k-major, so s-chunk 0's cur is complete ~25% into the run. Each tile:
// 16 bs-rows x 16 h4-cols x 128 i, encoding slice staged in SMEM (32KB).
// After a tile: threadfence + atomicAdd on its (k,b) flag.
// Consumers (bid >= 148): one (b, h-half) per CTA; for each of the 4
// s-chunks: spin until flag==8, load 16 cur values, run 80 recurrence steps
// (FFMA -> {FSETP || FADD} -> FSEL, ~12cyc/step), store z.
// Dependency is one-way (consumer->producer); all 148 producers are resident
// from wave 1 (distinct SMs), so no deadlock.
// ---------------------------------------------------------------------------
__global__ __launch_bounds__(256)
void fused_kernel(const float* __restrict__ x,
                  const float* __restrict__ enc,
                  float* __restrict__ out) {
    const int tid = threadIdx.x;
    float* cur = g_cur;

    if (blockIdx.x < NPROD) {
        // ------------------------- producer -------------------------
        __shared__ float4 senc[II][16];        // 128 x 16 float4 = 32KB

        const float4* __restrict__ x4 = reinterpret_cast<const float4*>(x);
        const float4* __restrict__ e4 = reinterpret_cast<const float4*>(enc);

        const int h4c = tid & 15;
        const int r   = tid >> 4;              // 0..15

        for (int j = blockIdx.x; j < NITEMS; j += NPROD) {
            const int k = j >> 7;              // s-chunk 0..3  (k-major order!)
            const int xs = (j >> 4) & 7;       // h-slice 0..7
            const int b  = j & 15;             // batch 0..15

            const int h4 = xs * 16 + h4c;      // 0..127
            const int bs = b * SS + k * 16 + r;

            // Stage this tile's encoding slice into SMEM.
            __syncthreads();                   // prior tile's readers done
            #pragma unroll
            for (int q = 0; q < 8; q++) {
                const int i = r + q * 16;
                senc[i][h4c] = e4[i * H4 + h4];
            }
            __syncthreads();

            const float4* xp = x4 + (long)bs * II * H4 + h4;
            float4 acc = make_float4(0.f, 0.f, 0.f, 0.f);

            #pragma unroll 8
            for (int i = 0; i < II; i++) {
                float4 xv = __ldcs(xp + i * H4);   // streaming, evict-first
                float4 ev = senc[i][h4c];
                acc.x = fmaf(xv.x, ev.x, acc.x);
                acc.y = fmaf(xv.y, ev.y, acc.y);
                acc.z = fmaf(xv.z, ev.z, acc.z);
                acc.w = fmaf(xv.w, ev.w, acc.w);
            }

            __stcg(reinterpret_cast<float4*>(cur) + (long)bs * H4 + h4, acc);

            __threadfence();                   // cur visible before flag
            __syncthreads();                   // all threads' stores issued
            if (tid == 0) atomicAdd(&g_flags[k * 16 + b], 1);
        }
    } else {
        // ------------------------- consumer -------------------------
        const int c    = blockIdx.x - NPROD;       // 0..31
        const int gtid = c * 256 + tid;            // 0..8191
        const int b    = gtid >> 9;                // /512
        const int h    = gtid & (HH - 1);

        const float* cp = cur + (long)b * SS * HH + h;
        float* op = out + (long)b * SS * TT * HH + h;
        volatile int* flags = g_flags;

        float v = 0.0f;
        for (int k = 0; k < 4; k++) {
            // Wait for all 8 h-slices of (k, b).
            while (flags[k * 16 + b] < 8) __nanosleep(64);
            __threadfence();                       // order cur reads after poll

            float cc[16];
            #pragma unroll
            for (int j = 0; j < 16; j++)
                cc[j] = __ldcg(cp + (k * 16 + j) * HH);

            float* ok = op + k * 16 * TT * HH;
            #pragma unroll
            for (int s = 0; s < 16; s++) {
                const float cs = cc[s];
                float* o = ok + s * TT * HH;
                #pragma unroll
                for (int t = 0; t < TT; t++) {
                    v = fmaf(0.9f, v, cs);           // v = ALPHA*v + i_t
                    const bool  p   = (v > 1.0f);    // FSETP
                    const float vm1 = v - 1.0f;      // FADD || FSETP
                    o[t * HH] = p ? 1.0f : 0.0f;     // z, off critical path
                    v = p ? vm1 : v;                 // FSEL
                }
            }
        }
    }
}

extern "C" void kernel_launch(void* const* d_in, const int* in_sizes, int n_in,
                              void* d_out, int out_size) {
    const float* x   = (const float*)d_in[0];   // [B,S,I,H] f32
    const float* enc = (const float*)d_in[1];   // [I,H] f32
    float* out = (float*)d_out;                 // [B, S*T, H] f32

    init_flags_kernel<<<1, 64>>>();
    fused_kernel<<<NPROD + NCONS, 256>>>(x, enc, out);
}

// round 15
// speedup vs baseline: 3.1914x; 3.1914x over previous
#include <cuda_runtime.h>

// Problem constants (fixed shapes from reference setup_inputs)
#define BB 16
#define SS 64
#define II 128
#define HH 512
#define TT 5
#define H4 (HH / 4)       // 128 float4 lanes across H
#define NSL 16            // h-slices per (I,H) row; each slice = 8 float4 = 32 floats
#define CH 16             // recurrence: s-steps per chunk

// ---------------------------------------------------------------------------
// Single fused kernel, NO inter-CTA communication.
// CTA = (b, slice of 32 h). 256 CTAs x 512 threads (same 131k-thread /
// ~28 warps/SM shape as the proven 5.9TB/s reduce).
//
// Phase 1 (all 512 threads): thread (s = tid>>3, h4c = tid&7) computes
//   cur[s][h4c] = sum_i x[b,s,i,slice*8+h4c] . enc[i, slice*8+h4c]
// with the 16KB encoding slice staged in SMEM and x streamed with .cs.
// Warp = 8 h4 x 4 s -> per i, four fully-used 128B transactions.
// cur goes to SMEM (8KB) — the 4MB global cur round-trip is gone.
//
// Phase 2 (warp 0 after one __syncthreads): 32 LIF chains, lane = h.
// Chunked: preload 16 cur values from SMEM (stride-1 across lanes, conflict-
// free), 80-step recurrence per chunk, chain ~12-13cyc/step
// (FFMA -> {FSETP || FADD} -> FSEL), z-select + 128B-coalesced STG off-path.
// Phase 2 of CTA A overlaps phase 1 of co-resident CTAs; only the chip-wide
// tail (~2-3us) is exposed.
// ---------------------------------------------------------------------------
__global__ __launch_bounds__(512)
void fused_kernel(const float* __restrict__ x,
                  const float* __restrict__ enc,
                  float* __restrict__ out) {
    __shared__ float4 senc4[II * 8];       // 128 i x 8 float4  = 16KB
    __shared__ float  scur[SS * 32];       // 64 s x 32 h       = 8KB

    const int tid = threadIdx.x;
    const int b   = blockIdx.x & 15;       // 0..15
    const int sl  = blockIdx.x >> 4;       // 0..15

    const float4* __restrict__ x4 = reinterpret_cast<const float4*>(x);
    const float4* __restrict__ e4 = reinterpret_cast<const float4*>(enc);

    // ---- stage encoding slice: 1024 float4, 2 per thread ----
    #pragma unroll
    for (int idx = tid; idx < II * 8; idx += 512) {
        senc4[idx] = e4[(idx >> 3) * H4 + sl * 8 + (idx & 7)];
    }
    __syncthreads();

    // ---- phase 1: reduction over i ----
    {
        const int h4c = tid & 7;           // 0..7 within slice
        const int s   = tid >> 3;          // 0..63

        const float4* xp = x4 + ((long)(b * SS + s) * II) * H4 + sl * 8 + h4c;

        float4 acc = make_float4(0.f, 0.f, 0.f, 0.f);
        #pragma unroll 8
        for (int i = 0; i < II; i++) {
            float4 xv = __ldcs(xp + i * H4);       // streaming, evict-first
            float4 ev = senc4[i * 8 + h4c];        // SMEM, conflict-free
            acc.x = fmaf(xv.x, ev.x, acc.x);
            acc.y = fmaf(xv.y, ev.y, acc.y);
            acc.z = fmaf(xv.z, ev.z, acc.z);
            acc.w = fmaf(xv.w, ev.w, acc.w);
        }
        reinterpret_cast<float4*>(scur)[s * 8 + h4c] = acc;
    }
    __syncthreads();

    // ---- phase 2: LIF recurrence, warp 0 only (lane = local h) ----
    if (tid < 32) {
        const int lane = tid;
        float* op = out + ((long)b * SS * TT) * HH + sl * 32 + lane;

        float v = 0.0f;
        for (int k = 0; k < SS / CH; k++) {
            float c[CH];
            #pragma unroll
            for (int j = 0; j < CH; j++)
                c[j] = scur[(k * CH + j) * 32 + lane];

            float* ok = op + (long)k * CH * TT * HH;
            #pragma unroll
            for (int s = 0; s < CH; s++) {
                const float cs = c[s];
                float* o = ok + s * TT * HH;
                #pragma unroll
                for (int t = 0; t < TT; t++) {
                    v = fmaf(0.9f, v, cs);           // v = ALPHA*v + i_t
                    const bool  p   = (v > 1.0f);    // FSETP
                    const float vm1 = v - 1.0f;      // FADD || FSETP
                    o[t * HH] = p ? 1.0f : 0.0f;     // z, off critical path
                    v = p ? vm1 : v;                 // FSEL
                }
            }
        }
    }
}

extern "C" void kernel_launch(void* const* d_in, const int* in_sizes, int n_in,
                              void* d_out, int out_size) {
    const float* x   = (const float*)d_in[0];   // [B,S,I,H] f32
    const float* enc = (const float*)d_in[1];   // [I,H] f32
    float* out = (float*)d_out;                 // [B, S*T, H] f32

    fused_kernel<<<BB * NSL, 512>>>(x, enc, out);   // 256 CTAs
}

// round 16
// speedup vs baseline: 5.0271x; 1.5752x over previous
#include <cuda_runtime.h>

// Problem constants (fixed shapes from reference setup_inputs)
#define BB 16
#define SS 64
#define II 128
#define HH 512
#define TT 5
#define H4 (HH / 4)       // 128 float4 lanes across H
#define NSL 16            // h-slices; each slice = 8 float4 = 32 floats
#define CH 16             // recurrence: s-steps per chunk

// ---------------------------------------------------------------------------
// Single fused kernel, no inter-CTA communication. CTA = (b, 32-wide h slice).
// 256 CTAs x 512 threads.
//
// R16 fix vs R15: __launch_bounds__(512, 2) (<=64 regs, was squeezed to 32
// which capped MLP_eff at ~4 and DRAM at 3.5TB/s) + explicit 8-deep load
// batches in phase 1 so 8 float4 LDGs are in flight per thread (MLP=8).
//
// Phase 1: thread (s = tid>>3, h4c = tid&7) reduces over i=128 with the 16KB
// encoding slice in SMEM; x streamed with .cs; cur -> SMEM (8KB, no global
// round-trip).
// Phase 2: warp 0 runs the 32 LIF chains (lane = h), chunked 16-s register
// preloads, ~12-13cyc/step chain (FFMA -> {FSETP || FADD} -> FSEL), z + STG
// off-path. Overlaps with co-resident CTAs' phase 1; only chip tail exposed.
// ---------------------------------------------------------------------------
__global__ __launch_bounds__(512, 2)
void fused_kernel(const float* __restrict__ x,
                  const float* __restrict__ enc,
                  float* __restrict__ out) {
    __shared__ float4 senc4[II * 8];       // 128 i x 8 float4  = 16KB
    __shared__ float  scur[SS * 32];       // 64 s x 32 h       = 8KB

    const int tid = threadIdx.x;
    const int b   = blockIdx.x & 15;       // 0..15
    const int sl  = blockIdx.x >> 4;       // 0..15

    const float4* __restrict__ x4 = reinterpret_cast<const float4*>(x);
    const float4* __restrict__ e4 = reinterpret_cast<const float4*>(enc);

    // ---- stage encoding slice: 1024 float4, 2 per thread ----
    #pragma unroll
    for (int idx = tid; idx < II * 8; idx += 512) {
        senc4[idx] = e4[(idx >> 3) * H4 + sl * 8 + (idx & 7)];
    }
    __syncthreads();

    // ---- phase 1: reduction over i, explicit MLP=8 batches ----
    {
        const int h4c = tid & 7;           // 0..7 within slice
        const int s   = tid >> 3;          // 0..63

        const float4* xp = x4 + ((long)(b * SS + s) * II) * H4 + sl * 8 + h4c;

        float4 acc = make_float4(0.f, 0.f, 0.f, 0.f);

        for (int i0 = 0; i0 < II; i0 += 8) {
            float4 xv[8];
            #pragma unroll
            for (int ii = 0; ii < 8; ii++)
                xv[ii] = __ldcs(xp + (i0 + ii) * H4);   // 8 LDGs in flight

            #pragma unroll
            for (int ii = 0; ii < 8; ii++) {
                const float4 ev = senc4[(i0 + ii) * 8 + h4c];
                acc.x = fmaf(xv[ii].x, ev.x, acc.x);
                acc.y = fmaf(xv[ii].y, ev.y, acc.y);
                acc.z = fmaf(xv[ii].z, ev.z, acc.z);
                acc.w = fmaf(xv[ii].w, ev.w, acc.w);
            }
        }
        reinterpret_cast<float4*>(scur)[s * 8 + h4c] = acc;
    }
    __syncthreads();

    // ---- phase 2: LIF recurrence, warp 0 only (lane = local h) ----
    if (tid < 32) {
        const int lane = tid;
        float* op = out + ((long)b * SS * TT) * HH + sl * 32 + lane;

        float v = 0.0f;
        for (int k = 0; k < SS / CH; k++) {
            float c[CH];
            #pragma unroll
            for (int j = 0; j < CH; j++)
                c[j] = scur[(k * CH + j) * 32 + lane];

            float* ok = op + (long)k * CH * TT * HH;
            #pragma unroll
            for (int s = 0; s < CH; s++) {
                const float cs = c[s];
                float* o = ok + s * TT * HH;
                #pragma unroll
                for (int t = 0; t < TT; t++) {
                    v = fmaf(0.9f, v, cs);           // v = ALPHA*v + i_t
                    const bool  p   = (v > 1.0f);    // FSETP
                    const float vm1 = v - 1.0f;      // FADD || FSETP
                    o[t * HH] = p ? 1.0f : 0.0f;     // z, off critical path
                    v = p ? vm1 : v;                 // FSEL
                }
            }
        }
    }
}

extern "C" void kernel_launch(void* const* d_in, const int* in_sizes, int n_in,
                              void* d_out, int out_size) {
    const float* x   = (const float*)d_in[0];   // [B,S,I,H] f32
    const float* enc = (const float*)d_in[1];   // [I,H] f32
    float* out = (float*)d_out;                 // [B, S*T, H] f32

    fused_kernel<<<BB * NSL, 512>>>(x, enc, out);   // 256 CTAs
}